// round 14
// baseline (speedup 1.0000x reference)
#include <cuda_runtime.h>
#include <cstdint>

// PCEN: EMA over time + pointwise compression.
// x: [B=32, T=8192, F=128] f32.  out same shape.
//
// Chunked EMA, 256-step warm-up (rel_err 2e-4 measured; accuracy-pinned).
// Task = (b, chunk, F-half): 32*32*2 = 2048 tasks; each is one warp running
// 32 lanes x float2 over 512 time rows (256 warm + 256 emit).
// Scheduling: 296 blocks (= 148 SMs x 2) x 8 warps = 2368 warp slots pull
// tasks from a global atomic queue -> ~13.8 active warps on EVERY SM,
// eliminating the 40-SM half-load straggler tail of the 256-block grid.

#define T_DIM   8192
#define F_DIM   128
#define B_DIM   32
#define L_CHUNK 256
#define N_CHUNK (T_DIM / L_CHUNK)   // 32
#define WARM    256
#define RDEPTH  16                  // ring depth (float2 rows in flight)
#define WARPS_PER_BLOCK 8           // 256 threads/block
#define N_TASKS (B_DIM * N_CHUNK * 2)   // 2048
#define N_BLOCKS 296                // 148 SMs x 2 resident blocks

#define EPS_C    1e-6f
#define S_C      0.025f
#define OMS_C    0.975f
#define ALPHA_C  0.98f
#define SQRT_DELTA_C 1.41421356237309515f  // sqrt(2.0)

__device__ int g_task_counter;

__global__ void reset_counter_kernel() { g_task_counter = 0; }

__device__ __forceinline__ float sqrt_approx(float x) {
    float y;
    asm("sqrt.approx.f32 %0, %1;" : "=f"(y) : "f"(x));
    return y;
}
__device__ __forceinline__ float lg2_approx(float x) {
    float y;
    asm("lg2.approx.f32 %0, %1;" : "=f"(y) : "f"(x));
    return y;
}
__device__ __forceinline__ float ex2_approx(float x) {
    float y;
    asm("ex2.approx.f32 %0, %1;" : "=f"(y) : "f"(x));
    return y;
}

// (m + eps)^(-alpha) via MUFU lg2/ex2
__device__ __forceinline__ float inv_pow_alpha(float m) {
    return ex2_approx(-ALPHA_C * lg2_approx(m + EPS_C));
}

__device__ __forceinline__ void ema_update(float2& m, const float2& xv) {
    m.x = fmaf(OMS_C, m.x, S_C * xv.x);
    m.y = fmaf(OMS_C, m.y, S_C * xv.y);
}

__device__ __forceinline__ float2 pcen_out(const float2& xv, const float2& m) {
    float2 o;
    o.x = sqrt_approx(fmaf(xv.x, inv_pow_alpha(m.x), 2.0f)) - SQRT_DELTA_C;
    o.y = sqrt_approx(fmaf(xv.y, inv_pow_alpha(m.y), 2.0f)) - SQRT_DELTA_C;
    return o;
}

__device__ __forceinline__ void store_cs(float2* p, const float2& v) {
    asm volatile("st.global.cs.v2.f32 [%0], {%1,%2};"
                 :: "l"(p), "f"(v.x), "f"(v.y) : "memory");
}

__device__ void run_task(int task, const float2* __restrict__ x,
                         float2* __restrict__ out, int lane) {
    const int half = task & 1;                    // which F half (0: f<64, 1: f>=64)
    const int cw   = task >> 1;
    const int b    = cw / N_CHUNK;
    const int c    = cw % N_CHUNK;

    const int warm = (c == 0) ? 0 : WARM;
    const int t_s  = c * L_CHUNK - warm;          // first time step this warp touches
    const int N    = L_CHUNK + warm;              // total steps (multiple of RDEPTH)

    const int ROWF2 = F_DIM / 2;                  // 64 float2 per time row

    const size_t base = (size_t)(b * T_DIM + t_s) * ROWF2 + half * 32 + lane;
    const float2* px = x   + base;
    float2*       po = out + base;

    // ---- prologue: fill ring ----
    float2 buf[RDEPTH];
#pragma unroll
    for (int i = 0; i < RDEPTH; i++)
        buf[i] = px[(size_t)i * ROWF2];

    // Seed m = x[t_s]; ema_update(m, x) with m == x is a fixed point, so the
    // first iteration needs no special case. Chunk 0: exact M[0] = x[0].
    float2 m = buf[0];

    int r = 0;

    // ---- warm-up tiles: EMA only, no output ----
    for (; r < warm; r += RDEPTH) {
#pragma unroll
        for (int i = 0; i < RDEPTH; i++) {
            float2 xv = buf[i];
            int nidx = min(r + RDEPTH + i, N - 1);   // clamp (redundant re-read, safe)
            buf[i] = px[(size_t)nidx * ROWF2];       // refill slot: depth-16 pipeline
            ema_update(m, xv);
        }
    }

    // ---- emit tiles: EMA + PCEN output ----
    for (; r < N; r += RDEPTH) {
#pragma unroll
        for (int i = 0; i < RDEPTH; i++) {
            float2 xv = buf[i];
            int nidx = min(r + RDEPTH + i, N - 1);
            buf[i] = px[(size_t)nidx * ROWF2];
            ema_update(m, xv);
            store_cs(po + (size_t)(r + i) * ROWF2, pcen_out(xv, m));
        }
    }
}

__global__ void __launch_bounds__(32 * WARPS_PER_BLOCK, 2)
pcen_kernel(const float2* __restrict__ x, float2* __restrict__ out) {
    const int lane = threadIdx.x & 31;

    // Warp-level dynamic work queue: lane 0 grabs a task id, broadcast.
    for (;;) {
        int task;
        if (lane == 0) task = atomicAdd(&g_task_counter, 1);
        task = __shfl_sync(0xFFFFFFFFu, task, 0);
        if (task >= N_TASKS) break;
        run_task(task, x, out, lane);
    }
}

extern "C" void kernel_launch(void* const* d_in, const int* in_sizes, int n_in,
                              void* d_out, int out_size) {
    (void)in_sizes; (void)n_in; (void)out_size;
    const float2* x = (const float2*)d_in[0];
    float2* o = (float2*)d_out;
    reset_counter_kernel<<<1, 1>>>();
    pcen_kernel<<<N_BLOCKS, 32 * WARPS_PER_BLOCK>>>(x, o);
}